// round 1
// baseline (speedup 1.0000x reference)
#include <cuda_runtime.h>

// Problem constants
#define BB 2
#define TT 4096
#define CC 768
#define HH 12
#define HS 64
#define MM (BB*TT)          // 8192
#define SCALE_F 0.125f      // HS^-0.5

// Scratch (allocation-free: __device__ globals)
__device__ float g_Q[BB*HH*TT*HS];    // [b,h,t,hs]
__device__ float g_K[BB*HH*TT*HS];
__device__ float g_V[BB*HH*TT*HS];
__device__ float g_att[MM*CC];        // [b,t,c] attention output

// ---------------------------------------------------------------------------
// SGEMM: C[m,n] = sum_k A[m,k] * W[n,k] + bias[n]
// A row-major [M,K], W row-major [N,K]. BM=BN=128, BK=8, 256 threads, 8x8 micro.
// MODE 0: A = x, scatter into g_Q/g_K/g_V ([b,h,t,hs]), bias = b_attn
// MODE 1: A = g_att (read directly), write Cout row-major, bias = b_proj
// ---------------------------------------------------------------------------
template<int MODE>
__global__ __launch_bounds__(256) void sgemm_kernel(
    const float* __restrict__ A, const float* __restrict__ W,
    const float* __restrict__ bias, float* __restrict__ Cout,
    int M, int N, int K)
{
    __shared__ float As[8][128];
    __shared__ float Bs[8][128];

    const int tid = threadIdx.x;
    const int tx = tid & 15;          // 0..15 (col groups)
    const int ty = tid >> 4;          // 0..15 (row groups)
    const int row0 = blockIdx.y * 128;
    const int col0 = blockIdx.x * 128;

    const int lrow = tid >> 1;        // 0..127
    const int lcol = (tid & 1) * 4;   // 0 or 4

    const float* Ap = (MODE == 0) ? A : g_att;
    const float* Arow = Ap + (size_t)(row0 + lrow) * K + lcol;
    const float* Wrow = W  + (size_t)(col0 + lrow) * K + lcol;

    float acc[8][8];
#pragma unroll
    for (int i = 0; i < 8; i++)
#pragma unroll
        for (int j = 0; j < 8; j++) acc[i][j] = 0.f;

    for (int kt = 0; kt < K; kt += 8) {
        float4 av = *(const float4*)(Arow + kt);
        float4 bv = *(const float4*)(Wrow + kt);
        As[lcol+0][lrow] = av.x; As[lcol+1][lrow] = av.y;
        As[lcol+2][lrow] = av.z; As[lcol+3][lrow] = av.w;
        Bs[lcol+0][lrow] = bv.x; Bs[lcol+1][lrow] = bv.y;
        Bs[lcol+2][lrow] = bv.z; Bs[lcol+3][lrow] = bv.w;
        __syncthreads();

#pragma unroll
        for (int k = 0; k < 8; k++) {
            float a[8], b[8];
            *(float4*)&a[0] = *(const float4*)&As[k][ty*8];
            *(float4*)&a[4] = *(const float4*)&As[k][ty*8+4];
            *(float4*)&b[0] = *(const float4*)&Bs[k][tx*8];
            *(float4*)&b[4] = *(const float4*)&Bs[k][tx*8+4];
#pragma unroll
            for (int i = 0; i < 8; i++)
#pragma unroll
                for (int j = 0; j < 8; j++)
                    acc[i][j] += a[i] * b[j];
        }
        __syncthreads();
    }

    // Epilogue. Thread columns: n = col0 + tx*8 + j (8 contiguous).
    float bvals[8];
#pragma unroll
    for (int j = 0; j < 8; j++) bvals[j] = bias[col0 + tx*8 + j];

#pragma unroll
    for (int i = 0; i < 8; i++) {
        const int m = row0 + ty*8 + i;
        float v[8];
#pragma unroll
        for (int j = 0; j < 8; j++) v[j] = acc[i][j] + bvals[j];

        if (MODE == 0) {
            // n block of 8 never straddles a head (8|64) or q/k/v (128|768) boundary
            const int n0 = col0 + tx*8;
            const int which = n0 / CC;
            const int r = n0 % CC;
            const int h = r / HS, e = r % HS;
            const int b = m / TT, t = m % TT;
            float* dst = (which == 0) ? g_Q : (which == 1) ? g_K : g_V;
            float* p = dst + (size_t)(((b*HH) + h)*TT + t)*HS + e;
            *(float4*)(p)     = make_float4(v[0], v[1], v[2], v[3]);
            *(float4*)(p + 4) = make_float4(v[4], v[5], v[6], v[7]);
        } else {
            float* p = Cout + (size_t)m * N + col0 + tx*8;
            *(float4*)(p)     = make_float4(v[0], v[1], v[2], v[3]);
            *(float4*)(p + 4) = make_float4(v[4], v[5], v[6], v[7]);
        }
    }
}

// ---------------------------------------------------------------------------
// Flash attention: grid (T/64, B*H), 256 threads.
// Thread (tx,ty) owns rows r_i = ty + 16*i (i<4) and cols c_j = tx + 16*j (j<4)
// of the 64x64 S tile and the 64x64 O tile. This stride-16 mapping makes all
// inner-loop shared loads bank-conflict-free (with +1 pad on Qs/Ks).
// SMEM: Qs[64][65] | Ks[64][65] (reused for P) | Vs[64][64]  = 49664 B dynamic.
// ---------------------------------------------------------------------------
#define ATTN_SMEM ((64*65 + 64*65 + 64*64) * 4)

__global__ __launch_bounds__(256) void attn_kernel()
{
    extern __shared__ float sm[];
    float (*Qs)[65] = (float(*)[65])sm;
    float (*Ks)[65] = (float(*)[65])(sm + 64*65);
    float (*Vs)[64] = (float(*)[64])(sm + 2*64*65);

    const int tid = threadIdx.x;
    const int tx = tid & 15;
    const int ty = tid >> 4;
    const int qi = blockIdx.x;          // q tile index
    const int bh = blockIdx.y;          // b*H + h
    const int q0 = qi * 64;

    const float* Qg = g_Q + (size_t)bh * TT * HS;
    const float* Kg = g_K + (size_t)bh * TT * HS;
    const float* Vg = g_V + (size_t)bh * TT * HS;

    // Load Q tile (64x64): 256 threads x 16 floats
    {
        const int r = tid >> 2;
        const int c = (tid & 3) * 16;
#pragma unroll
        for (int u = 0; u < 4; u++) {
            float4 v = *(const float4*)(Qg + (size_t)(q0 + r)*HS + c + u*4);
            Qs[r][c + u*4 + 0] = v.x; Qs[r][c + u*4 + 1] = v.y;
            Qs[r][c + u*4 + 2] = v.z; Qs[r][c + u*4 + 3] = v.w;
        }
    }

    float acc_o[4][4];
    float mi[4], li[4];
#pragma unroll
    for (int i = 0; i < 4; i++) {
        mi[i] = -1e30f; li[i] = 0.f;
#pragma unroll
        for (int j = 0; j < 4; j++) acc_o[i][j] = 0.f;
    }

    for (int kj = 0; kj <= qi; kj++) {
        const int k0 = kj * 64;
        __syncthreads();   // prior iteration's P/V reads done (and Q load on iter 0)

        // Load K and V tiles
        {
            const int r = tid >> 2;
            const int c = (tid & 3) * 16;
#pragma unroll
            for (int u = 0; u < 4; u++) {
                float4 kv = *(const float4*)(Kg + (size_t)(k0 + r)*HS + c + u*4);
                float4 vv = *(const float4*)(Vg + (size_t)(k0 + r)*HS + c + u*4);
                Ks[r][c + u*4 + 0] = kv.x; Ks[r][c + u*4 + 1] = kv.y;
                Ks[r][c + u*4 + 2] = kv.z; Ks[r][c + u*4 + 3] = kv.w;
                Vs[r][c + u*4 + 0] = vv.x; Vs[r][c + u*4 + 1] = vv.y;
                Vs[r][c + u*4 + 2] = vv.z; Vs[r][c + u*4 + 3] = vv.w;
            }
        }
        __syncthreads();

        // S = Q K^T
        float s[4][4];
#pragma unroll
        for (int i = 0; i < 4; i++)
#pragma unroll
            for (int j = 0; j < 4; j++) s[i][j] = 0.f;

#pragma unroll 8
        for (int k = 0; k < 64; k++) {
            float qa[4], kb[4];
#pragma unroll
            for (int i = 0; i < 4; i++) qa[i] = Qs[ty + 16*i][k];
#pragma unroll
            for (int j = 0; j < 4; j++) kb[j] = Ks[tx + 16*j][k];
#pragma unroll
            for (int i = 0; i < 4; i++)
#pragma unroll
                for (int j = 0; j < 4; j++)
                    s[i][j] += qa[i] * kb[j];
        }

        const bool diag = (kj == qi);
#pragma unroll
        for (int i = 0; i < 4; i++) {
#pragma unroll
            for (int j = 0; j < 4; j++) {
                s[i][j] *= SCALE_F;
                if (diag && (k0 + tx + 16*j) > (q0 + ty + 16*i))
                    s[i][j] = -1e30f;
            }
        }

        // Online softmax (row stats across tx via shuffle; lane bits 0..3 = tx)
#pragma unroll
        for (int i = 0; i < 4; i++) {
            float mx = s[i][0];
#pragma unroll
            for (int j = 1; j < 4; j++) mx = fmaxf(mx, s[i][j]);
            mx = fmaxf(mx, __shfl_xor_sync(0xffffffffu, mx, 1));
            mx = fmaxf(mx, __shfl_xor_sync(0xffffffffu, mx, 2));
            mx = fmaxf(mx, __shfl_xor_sync(0xffffffffu, mx, 4));
            mx = fmaxf(mx, __shfl_xor_sync(0xffffffffu, mx, 8));
            const float mnew = fmaxf(mi[i], mx);
            const float corr = __expf(mi[i] - mnew);
            li[i] *= corr;
#pragma unroll
            for (int j = 0; j < 4; j++) acc_o[i][j] *= corr;
            float sum = 0.f;
#pragma unroll
            for (int j = 0; j < 4; j++) {
                s[i][j] = __expf(s[i][j] - mnew);
                sum += s[i][j];
            }
            sum += __shfl_xor_sync(0xffffffffu, sum, 1);
            sum += __shfl_xor_sync(0xffffffffu, sum, 2);
            sum += __shfl_xor_sync(0xffffffffu, sum, 4);
            sum += __shfl_xor_sync(0xffffffffu, sum, 8);
            li[i] += sum;
            mi[i] = mnew;
        }

        __syncthreads();   // all S reads of Ks complete
        // P -> Ks buffer
#pragma unroll
        for (int i = 0; i < 4; i++)
#pragma unroll
            for (int j = 0; j < 4; j++)
                Ks[ty + 16*i][tx + 16*j] = s[i][j];
        __syncthreads();

        // O += P V
#pragma unroll 8
        for (int k = 0; k < 64; k++) {
            float pa[4], vb[4];
#pragma unroll
            for (int i = 0; i < 4; i++) pa[i] = Ks[ty + 16*i][k];
#pragma unroll
            for (int j = 0; j < 4; j++) vb[j] = Vs[k][tx + 16*j];
#pragma unroll
            for (int i = 0; i < 4; i++)
#pragma unroll
                for (int j = 0; j < 4; j++)
                    acc_o[i][j] += pa[i] * vb[j];
        }
    }

    // Write O / l  into g_att [b,t,c] with c = h*64 + e
    const int b = bh / HH, h = bh % HH;
#pragma unroll
    for (int i = 0; i < 4; i++) {
        const int t = q0 + ty + 16*i;
        const float inv = 1.f / li[i];
        float* dst = g_att + (size_t)(b*TT + t)*CC + h*HS;
#pragma unroll
        for (int j = 0; j < 4; j++)
            dst[tx + 16*j] = acc_o[i][j] * inv;
    }
}

// ---------------------------------------------------------------------------
extern "C" void kernel_launch(void* const* d_in, const int* in_sizes, int n_in,
                              void* d_out, int out_size)
{
    const float* x      = (const float*)d_in[0];
    const float* w_attn = (const float*)d_in[1];
    const float* b_attn = (const float*)d_in[2];
    const float* w_proj = (const float*)d_in[3];
    const float* b_proj = (const float*)d_in[4];
    float* out = (float*)d_out;

    (void)in_sizes; (void)n_in; (void)out_size;

    // 1) QKV projection: [8192,768] x [2304,768]^T -> scatter to g_Q/g_K/g_V
    dim3 g1(3*CC/128, MM/128);
    sgemm_kernel<0><<<g1, 256>>>(x, w_attn, b_attn, nullptr, MM, 3*CC, CC);

    // 2) Flash attention
    cudaFuncSetAttribute(attn_kernel,
                         cudaFuncAttributeMaxDynamicSharedMemorySize, ATTN_SMEM);
    attn_kernel<<<dim3(TT/64, BB*HH), 256, ATTN_SMEM>>>();

    // 3) Output projection: g_att x w_proj^T + b_proj -> out
    dim3 g3(CC/128, MM/128);
    sgemm_kernel<1><<<g3, 256>>>(nullptr, w_proj, b_proj, out, MM, CC, CC);
}

// round 3
// speedup vs baseline: 2.8249x; 2.8249x over previous
#include <cuda_runtime.h>
#include <cuda_bf16.h>
#include <cstdint>

// Problem constants
#define BB 2
#define TT 4096
#define CC 768
#define HH 12
#define HS 64
#define MM (BB*TT)          // 8192
#define KKC 768
#define SCALE_F 0.125f      // HS^-0.5

// ---------------------------------------------------------------------------
// Scratch (allocation-free: __device__ globals)
// ---------------------------------------------------------------------------
__device__ float g_Q[BB*HH*TT*HS];    // [b,h,t,hs] fp32
__device__ float g_K[BB*HH*TT*HS];
__device__ float g_V[BB*HH*TT*HS];
__device__ float g_att[MM*CC];        // [b,t,c] attention output fp32

// bf16 hi/lo split operands for the dense GEMMs
__device__ __nv_bfloat16 g_xh[MM*CC],    g_xl[MM*CC];
__device__ __nv_bfloat16 g_wah[3*CC*CC], g_wal[3*CC*CC];
__device__ __nv_bfloat16 g_wph[CC*CC],   g_wpl[CC*CC];
__device__ __nv_bfloat16 g_ah[MM*CC],    g_al[MM*CC];

// ---------------------------------------------------------------------------
// Helpers (baseline PTX only: ldmatrix + mma.sync, valid on sm_100 base)
// ---------------------------------------------------------------------------
__device__ __forceinline__ uint32_t smem_u32(const void* p) {
    uint32_t r;
    asm("{ .reg .u64 t; cvta.to.shared.u64 t, %1; cvt.u32.u64 %0, t; }" : "=r"(r) : "l"(p));
    return r;
}
__device__ __forceinline__ void mma16816(float c[4], const uint32_t a[4], const uint32_t b[2]) {
    asm volatile("mma.sync.aligned.m16n8k16.row.col.f32.bf16.bf16.f32 "
                 "{%0,%1,%2,%3}, {%4,%5,%6,%7}, {%8,%9}, {%0,%1,%2,%3};"
                 : "+f"(c[0]), "+f"(c[1]), "+f"(c[2]), "+f"(c[3])
                 : "r"(a[0]), "r"(a[1]), "r"(a[2]), "r"(a[3]), "r"(b[0]), "r"(b[1]));
}
__device__ __forceinline__ void ldsm_x4(uint32_t r[4], uint32_t addr) {
    asm volatile("ldmatrix.sync.aligned.m8n8.x4.shared.b16 {%0,%1,%2,%3}, [%4];"
                 : "=r"(r[0]), "=r"(r[1]), "=r"(r[2]), "=r"(r[3]) : "r"(addr));
}
__device__ __forceinline__ void ldsm_x2(uint32_t r[2], uint32_t addr) {
    asm volatile("ldmatrix.sync.aligned.m8n8.x2.shared.b16 {%0,%1}, [%2];"
                 : "=r"(r[0]), "=r"(r[1]) : "r"(addr));
}
__device__ __forceinline__ void ldsm_x2t(uint32_t r[2], uint32_t addr) {
    asm volatile("ldmatrix.sync.aligned.m8n8.x2.trans.shared.b16 {%0,%1}, [%2];"
                 : "=r"(r[0]), "=r"(r[1]) : "r"(addr));
}
__device__ __forceinline__ uint32_t pack_bf2(__nv_bfloat16 lo, __nv_bfloat16 hi) {
    return ((uint32_t)__bfloat16_as_ushort(hi) << 16) | (uint32_t)__bfloat16_as_ushort(lo);
}
// split (a,b) fp32 pair -> packed bf16x2 hi and lo words
__device__ __forceinline__ void pack_split(float a, float b, uint32_t& h, uint32_t& l) {
    __nv_bfloat16 ha = __float2bfloat16(a), hb = __float2bfloat16(b);
    __nv_bfloat16 la = __float2bfloat16(a - __bfloat162float(ha));
    __nv_bfloat16 lb = __float2bfloat16(b - __bfloat162float(hb));
    h = pack_bf2(ha, hb);
    l = pack_bf2(la, lb);
}

// ---------------------------------------------------------------------------
// Split fp32 -> bf16 hi + bf16 lo (elementwise)
// ---------------------------------------------------------------------------
__global__ __launch_bounds__(256) void split_kernel(
    const float* __restrict__ in, __nv_bfloat16* __restrict__ hi,
    __nv_bfloat16* __restrict__ lo, int n)
{
    int i = (blockIdx.x * 256 + threadIdx.x) * 4;
    if (i >= n) return;
    float4 v = *(const float4*)(in + i);
    uint2 hv, lv;
    pack_split(v.x, v.y, hv.x, lv.x);
    pack_split(v.z, v.w, hv.y, lv.y);
    *(uint2*)(hi + i) = hv;
    *(uint2*)(lo + i) = lv;
}

// ---------------------------------------------------------------------------
// Dense GEMM via mma.sync: C[m,n] = sum_k A[m,k]*W[n,k] + bias[n]
// 128x128 CTA tile, BK=32, 8 warps (4 m-warps x 2 n-warps), warp tile 32x64.
// MODE 0: scatter into g_Q/g_K/g_V.  MODE 1: row-major Cout.
// ---------------------------------------------------------------------------
#define GPAD 40   // smem row stride in bf16 (32 data + 8 pad)

template<int MODE>
__global__ __launch_bounds__(256) void mma_gemm(
    const __nv_bfloat16* __restrict__ Ah, const __nv_bfloat16* __restrict__ Al,
    const __nv_bfloat16* __restrict__ Bh, const __nv_bfloat16* __restrict__ Bl,
    const float* __restrict__ bias, float* __restrict__ Cout, int N)
{
    __shared__ __nv_bfloat16 sA[2][128 * GPAD];
    __shared__ __nv_bfloat16 sB[2][128 * GPAD];

    const int tid  = threadIdx.x;
    const int lane = tid & 31;
    const int wid  = tid >> 5;
    const int wm   = wid & 3;          // 0..3 -> m offset 32*wm
    const int wn   = wid >> 2;         // 0..1 -> n offset 64*wn
    const int row0 = blockIdx.y * 128;
    const int col0 = blockIdx.x * 128;
    const int grp  = lane >> 2, qp = lane & 3;

    float acc[2][8][4];
#pragma unroll
    for (int mt = 0; mt < 2; mt++)
#pragma unroll
        for (int j = 0; j < 8; j++)
#pragma unroll
            for (int c = 0; c < 4; c++) acc[mt][j][c] = 0.f;

    // ldmatrix addresses (computed once)
    const int asel = lane >> 3;
    const int arow_off = (asel & 1) * 8 + (lane & 7);
    const int acol_off = (lane >> 4) * 8;
    const int brow = wn * 64 + (lane & 7);
    const int bcol_off = ((lane >> 3) & 1) * 8;

    for (int kt = 0; kt < KKC; kt += 32) {
        __syncthreads();
        // fill: 4 matrices x 512 uint4 (8 bf16 each)
#pragma unroll
        for (int u = 0; u < 2; u++) {
            const int idx = tid + u * 256;
            const int r = idx >> 2, c8 = (idx & 3) * 8;
            *(uint4*)&sA[0][r * GPAD + c8] = *(const uint4*)&Ah[(size_t)(row0 + r) * KKC + kt + c8];
            *(uint4*)&sA[1][r * GPAD + c8] = *(const uint4*)&Al[(size_t)(row0 + r) * KKC + kt + c8];
            *(uint4*)&sB[0][r * GPAD + c8] = *(const uint4*)&Bh[(size_t)(col0 + r) * KKC + kt + c8];
            *(uint4*)&sB[1][r * GPAD + c8] = *(const uint4*)&Bl[(size_t)(col0 + r) * KKC + kt + c8];
        }
        __syncthreads();

#pragma unroll
        for (int ks = 0; ks < 2; ks++) {
            uint32_t afh[2][4], afl[2][4];
#pragma unroll
            for (int mt = 0; mt < 2; mt++) {
                const int arow = wm * 32 + mt * 16 + arow_off;
                const int acol = ks * 16 + acol_off;
                ldsm_x4(afh[mt], smem_u32(&sA[0][arow * GPAD + acol]));
                ldsm_x4(afl[mt], smem_u32(&sA[1][arow * GPAD + acol]));
            }
#pragma unroll
            for (int j = 0; j < 8; j++) {
                uint32_t bh2[2], bl2[2];
                const int bro = (brow + j * 8) * GPAD + ks * 16 + bcol_off;
                ldsm_x2(bh2, smem_u32(&sB[0][bro]));
                ldsm_x2(bl2, smem_u32(&sB[1][bro]));
#pragma unroll
                for (int mt = 0; mt < 2; mt++) {
                    mma16816(acc[mt][j], afh[mt], bh2);
                    mma16816(acc[mt][j], afh[mt], bl2);
                    mma16816(acc[mt][j], afl[mt], bh2);
                }
            }
        }
    }

    // Epilogue
#pragma unroll
    for (int mt = 0; mt < 2; mt++) {
#pragma unroll
        for (int j = 0; j < 8; j++) {
            const int n = col0 + wn * 64 + j * 8 + qp * 2;
            const float b0 = bias[n], b1 = bias[n + 1];
#pragma unroll
            for (int rr = 0; rr < 2; rr++) {
                const int m = row0 + wm * 32 + mt * 16 + grp + rr * 8;
                float v0 = acc[mt][j][rr * 2 + 0] + b0;
                float v1 = acc[mt][j][rr * 2 + 1] + b1;
                if (MODE == 0) {
                    const int which = n / CC;
                    const int rrm = n % CC;
                    const int h = rrm / HS, e = rrm % HS;
                    const int bb = m / TT, t = m % TT;
                    float* dst = ((which == 0) ? g_Q : (which == 1) ? g_K : g_V)
                                 + ((size_t)(bb * HH + h) * TT + t) * HS + e;
                    *(float2*)dst = make_float2(v0, v1);
                } else {
                    float* p = Cout + (size_t)m * N + n;
                    *(float2*)p = make_float2(v0, v1);
                }
            }
        }
    }
}

// ---------------------------------------------------------------------------
// Flash attention via mma.sync. Grid (TT/128, BB*HH), 256 threads (8 warps).
// Each warp owns 16 q rows. Bc=64 keys per iteration. Split-bf16, fp32 accum.
// ---------------------------------------------------------------------------
#define APAD 72   // smem row stride in bf16 (64 + 8 pad)

__global__ __launch_bounds__(256) void attn_mma()
{
    __shared__ __nv_bfloat16 Ksh[64 * APAD], Ksl[64 * APAD];
    __shared__ __nv_bfloat16 Vsh[64 * APAD], Vsl[64 * APAD];

    const int tid  = threadIdx.x;
    const int lane = tid & 31;
    const int wid  = tid >> 5;
    const int qi   = blockIdx.x;
    const int bh   = blockIdx.y;
    const int q0   = qi * 128;
    const int grp  = lane >> 2, qp = lane & 3;
    const int wr0  = q0 + wid * 16;     // warp's first q row

    const float* Qg = g_Q + (size_t)bh * TT * HS;
    const float* Kg = g_K + (size_t)bh * TT * HS;
    const float* Vg = g_V + (size_t)bh * TT * HS;

    // Preload Q fragments (scale folded), 4 k-steps x (a0..a3) hi/lo
    uint32_t qh[4][4], ql[4][4];
#pragma unroll
    for (int ks = 0; ks < 4; ks++) {
        const int c0 = ks * 16 + qp * 2;
        const int r0 = wr0 + grp, r1 = r0 + 8;
        float2 v0 = *(const float2*)(Qg + (size_t)r0 * HS + c0);
        float2 v1 = *(const float2*)(Qg + (size_t)r1 * HS + c0);
        float2 v2 = *(const float2*)(Qg + (size_t)r0 * HS + c0 + 8);
        float2 v3 = *(const float2*)(Qg + (size_t)r1 * HS + c0 + 8);
        pack_split(v0.x * SCALE_F, v0.y * SCALE_F, qh[ks][0], ql[ks][0]);
        pack_split(v1.x * SCALE_F, v1.y * SCALE_F, qh[ks][1], ql[ks][1]);
        pack_split(v2.x * SCALE_F, v2.y * SCALE_F, qh[ks][2], ql[ks][2]);
        pack_split(v3.x * SCALE_F, v3.y * SCALE_F, qh[ks][3], ql[ks][3]);
    }

    float oacc[8][4];
    float mi[2] = {-1e30f, -1e30f}, li[2] = {0.f, 0.f};
#pragma unroll
    for (int j = 0; j < 8; j++)
#pragma unroll
        for (int c = 0; c < 4; c++) oacc[j][c] = 0.f;

    // ldmatrix address offsets
    const int kb_row = (lane & 7);
    const int kb_col = ((lane >> 3) & 1) * 8;

    const int niters = 2 * qi + 2;
    for (int kj = 0; kj < niters; kj++) {
        const int k0 = kj * 64;
        __syncthreads();
        // Fill K/V tiles (fp32 -> split bf16)
#pragma unroll
        for (int u = 0; u < 4; u++) {
            const int idx = tid + u * 256;
            const int r = idx >> 4, c4 = (idx & 15) * 4;
            float4 kv = *(const float4*)(Kg + (size_t)(k0 + r) * HS + c4);
            float4 vv = *(const float4*)(Vg + (size_t)(k0 + r) * HS + c4);
            uint2 kh2, kl2, vh2, vl2;
            pack_split(kv.x, kv.y, kh2.x, kl2.x);
            pack_split(kv.z, kv.w, kh2.y, kl2.y);
            pack_split(vv.x, vv.y, vh2.x, vl2.x);
            pack_split(vv.z, vv.w, vh2.y, vl2.y);
            *(uint2*)&Ksh[r * APAD + c4] = kh2;
            *(uint2*)&Ksl[r * APAD + c4] = kl2;
            *(uint2*)&Vsh[r * APAD + c4] = vh2;
            *(uint2*)&Vsl[r * APAD + c4] = vl2;
        }
        __syncthreads();

        if (k0 > wr0 + 15) continue;   // fully masked for this warp

        // S = Q K^T (fp32 accum)
        float sacc[8][4];
#pragma unroll
        for (int j = 0; j < 8; j++)
#pragma unroll
            for (int c = 0; c < 4; c++) sacc[j][c] = 0.f;

#pragma unroll
        for (int ks = 0; ks < 4; ks++) {
#pragma unroll
            for (int j = 0; j < 8; j++) {
                uint32_t kbh[2], kbl[2];
                const int off = (j * 8 + kb_row) * APAD + ks * 16 + kb_col;
                ldsm_x2(kbh, smem_u32(&Ksh[off]));
                ldsm_x2(kbl, smem_u32(&Ksl[off]));
                mma16816(sacc[j], qh[ks], kbh);
                mma16816(sacc[j], qh[ks], kbl);
                mma16816(sacc[j], ql[ks], kbh);
            }
        }

        // Causal mask (only partially-masked tiles)
        if (k0 + 63 > wr0) {
#pragma unroll
            for (int j = 0; j < 8; j++) {
#pragma unroll
                for (int c = 0; c < 4; c++) {
                    const int col = k0 + j * 8 + qp * 2 + (c & 1);
                    const int row = wr0 + grp + ((c >> 1) * 8);
                    if (col > row) sacc[j][c] = -1e30f;
                }
            }
        }

        // Online softmax (two rows per thread)
#pragma unroll
        for (int rr = 0; rr < 2; rr++) {
            float mx = -1e30f;
#pragma unroll
            for (int j = 0; j < 8; j++) {
                mx = fmaxf(mx, sacc[j][rr * 2]);
                mx = fmaxf(mx, sacc[j][rr * 2 + 1]);
            }
            mx = fmaxf(mx, __shfl_xor_sync(0xffffffffu, mx, 1));
            mx = fmaxf(mx, __shfl_xor_sync(0xffffffffu, mx, 2));
            const float mnew = fmaxf(mi[rr], mx);
            const float corr = __expf(mi[rr] - mnew);
            float sum = 0.f;
#pragma unroll
            for (int j = 0; j < 8; j++) {
                float p0 = __expf(sacc[j][rr * 2]     - mnew);
                float p1 = __expf(sacc[j][rr * 2 + 1] - mnew);
                sacc[j][rr * 2] = p0; sacc[j][rr * 2 + 1] = p1;
                sum += p0 + p1;
            }
            sum += __shfl_xor_sync(0xffffffffu, sum, 1);
            sum += __shfl_xor_sync(0xffffffffu, sum, 2);
            li[rr] = li[rr] * corr + sum;
            mi[rr] = mnew;
#pragma unroll
            for (int j = 0; j < 8; j++) {
                oacc[j][rr * 2]     *= corr;
                oacc[j][rr * 2 + 1] *= corr;
            }
        }

        // P fragments in-register (C-frag -> A-frag mapping is identity)
        uint32_t ph[4][4], pl[4][4];
#pragma unroll
        for (int ks = 0; ks < 4; ks++) {
            const int j0 = 2 * ks, j1 = 2 * ks + 1;
            pack_split(sacc[j0][0], sacc[j0][1], ph[ks][0], pl[ks][0]);
            pack_split(sacc[j0][2], sacc[j0][3], ph[ks][1], pl[ks][1]);
            pack_split(sacc[j1][0], sacc[j1][1], ph[ks][2], pl[ks][2]);
            pack_split(sacc[j1][2], sacc[j1][3], ph[ks][3], pl[ks][3]);
        }

        // O += P V   (V via ldmatrix.trans)
#pragma unroll
        for (int ks = 0; ks < 4; ks++) {
#pragma unroll
            for (int jo = 0; jo < 8; jo++) {
                uint32_t vbh[2], vbl[2];
                const int off = (ks * 16 + kb_row + kb_col) * APAD + jo * 8;
                ldsm_x2t(vbh, smem_u32(&Vsh[off]));
                ldsm_x2t(vbl, smem_u32(&Vsl[off]));
                mma16816(oacc[jo], ph[ks], vbh);
                mma16816(oacc[jo], ph[ks], vbl);
                mma16816(oacc[jo], pl[ks], vbh);
            }
        }
    }

    // Write O / l into g_att [b,t,c], c = h*64 + e
    const int b = bh / HH, h = bh % HH;
#pragma unroll
    for (int rr = 0; rr < 2; rr++) {
        const int t = wr0 + grp + rr * 8;
        const float inv = 1.f / li[rr];
        float* dst = g_att + (size_t)(b * TT + t) * CC + h * HS;
#pragma unroll
        for (int jo = 0; jo < 8; jo++) {
            float2 v = make_float2(oacc[jo][rr * 2] * inv, oacc[jo][rr * 2 + 1] * inv);
            *(float2*)(dst + jo * 8 + qp * 2) = v;
        }
    }
}

// ---------------------------------------------------------------------------
extern "C" void kernel_launch(void* const* d_in, const int* in_sizes, int n_in,
                              void* d_out, int out_size)
{
    const float* x      = (const float*)d_in[0];
    const float* w_attn = (const float*)d_in[1];
    const float* b_attn = (const float*)d_in[2];
    const float* w_proj = (const float*)d_in[3];
    const float* b_proj = (const float*)d_in[4];
    float* out = (float*)d_out;
    (void)in_sizes; (void)n_in; (void)out_size;

    __nv_bfloat16 *xh, *xl, *wah, *wal, *wph, *wpl, *ah, *al;
    cudaGetSymbolAddress((void**)&xh,  g_xh);  cudaGetSymbolAddress((void**)&xl,  g_xl);
    cudaGetSymbolAddress((void**)&wah, g_wah); cudaGetSymbolAddress((void**)&wal, g_wal);
    cudaGetSymbolAddress((void**)&wph, g_wph); cudaGetSymbolAddress((void**)&wpl, g_wpl);
    cudaGetSymbolAddress((void**)&ah,  g_ah);  cudaGetSymbolAddress((void**)&al,  g_al);
    float* att; cudaGetSymbolAddress((void**)&att, g_att);

    // 0) split inputs to bf16 hi/lo
    split_kernel<<<(MM*CC/4 + 255)/256, 256>>>(x, xh, xl, MM*CC);
    split_kernel<<<(3*CC*CC/4 + 255)/256, 256>>>(w_attn, wah, wal, 3*CC*CC);
    split_kernel<<<(CC*CC/4 + 255)/256, 256>>>(w_proj, wph, wpl, CC*CC);

    // 1) QKV projection (tensor cores) -> scatter g_Q/g_K/g_V
    mma_gemm<0><<<dim3(3*CC/128, MM/128), 256>>>(xh, xl, wah, wal, b_attn, nullptr, 3*CC);

    // 2) Flash attention (tensor cores)
    attn_mma<<<dim3(TT/128, BB*HH), 256>>>();

    // 3) split attention output, then output projection (tensor cores)
    split_kernel<<<(MM*CC/4 + 255)/256, 256>>>(att, ah, al, MM*CC);
    mma_gemm<1><<<dim3(CC/128, MM/128), 256>>>(ah, al, wph, wpl, b_proj, out, CC);
}

// round 4
// speedup vs baseline: 3.3834x; 1.1977x over previous
#include <cuda_runtime.h>
#include <cuda_bf16.h>
#include <cstdint>

// Problem constants
#define BB 2
#define TT 4096
#define CC 768
#define HH 12
#define HS 64
#define MM (BB*TT)          // 8192
#define KKC 768
#define SCALE_F 0.125f      // HS^-0.5

// ---------------------------------------------------------------------------
// Scratch (allocation-free: __device__ globals) — all bf16 hi/lo pairs
// ---------------------------------------------------------------------------
__device__ __nv_bfloat16 g_Qh[BB*HH*TT*HS], g_Ql[BB*HH*TT*HS];   // scaled Q
__device__ __nv_bfloat16 g_Kh[BB*HH*TT*HS], g_Kl[BB*HH*TT*HS];
__device__ __nv_bfloat16 g_Vh[BB*HH*TT*HS], g_Vl[BB*HH*TT*HS];
__device__ __nv_bfloat16 g_xh[MM*CC],    g_xl[MM*CC];
__device__ __nv_bfloat16 g_wah[3*CC*CC], g_wal[3*CC*CC];
__device__ __nv_bfloat16 g_wph[CC*CC],   g_wpl[CC*CC];
__device__ __nv_bfloat16 g_ah[MM*CC],    g_al[MM*CC];            // attn out

// ---------------------------------------------------------------------------
// Helpers (baseline PTX: ldmatrix + mma.sync + cp.async — all sm_100-base ok)
// ---------------------------------------------------------------------------
__device__ __forceinline__ uint32_t smem_u32(const void* p) {
    uint32_t r;
    asm("{ .reg .u64 t; cvta.to.shared.u64 t, %1; cvt.u32.u64 %0, t; }" : "=r"(r) : "l"(p));
    return r;
}
__device__ __forceinline__ void mma16816(float c[4], const uint32_t a[4], const uint32_t b[2]) {
    asm volatile("mma.sync.aligned.m16n8k16.row.col.f32.bf16.bf16.f32 "
                 "{%0,%1,%2,%3}, {%4,%5,%6,%7}, {%8,%9}, {%0,%1,%2,%3};"
                 : "+f"(c[0]), "+f"(c[1]), "+f"(c[2]), "+f"(c[3])
                 : "r"(a[0]), "r"(a[1]), "r"(a[2]), "r"(a[3]), "r"(b[0]), "r"(b[1]));
}
__device__ __forceinline__ void ldsm_x4(uint32_t r[4], uint32_t addr) {
    asm volatile("ldmatrix.sync.aligned.m8n8.x4.shared.b16 {%0,%1,%2,%3}, [%4];"
                 : "=r"(r[0]), "=r"(r[1]), "=r"(r[2]), "=r"(r[3]) : "r"(addr));
}
__device__ __forceinline__ void ldsm_x2(uint32_t r[2], uint32_t addr) {
    asm volatile("ldmatrix.sync.aligned.m8n8.x2.shared.b16 {%0,%1}, [%2];"
                 : "=r"(r[0]), "=r"(r[1]) : "r"(addr));
}
__device__ __forceinline__ void ldsm_x2t(uint32_t r[2], uint32_t addr) {
    asm volatile("ldmatrix.sync.aligned.m8n8.x2.trans.shared.b16 {%0,%1}, [%2];"
                 : "=r"(r[0]), "=r"(r[1]) : "r"(addr));
}
__device__ __forceinline__ void cp16(uint32_t smem, const void* g) {
    asm volatile("cp.async.cg.shared.global [%0], [%1], 16;" :: "r"(smem), "l"(g));
}
#define CP_COMMIT() asm volatile("cp.async.commit_group;" ::: "memory")
#define CP_WAIT1()  asm volatile("cp.async.wait_group 1;" ::: "memory")
#define CP_WAIT0()  asm volatile("cp.async.wait_group 0;" ::: "memory")

__device__ __forceinline__ uint32_t pack_bf2(__nv_bfloat16 lo, __nv_bfloat16 hi) {
    return ((uint32_t)__bfloat16_as_ushort(hi) << 16) | (uint32_t)__bfloat16_as_ushort(lo);
}
__device__ __forceinline__ void pack_split(float a, float b, uint32_t& h, uint32_t& l) {
    __nv_bfloat16 ha = __float2bfloat16(a), hb = __float2bfloat16(b);
    __nv_bfloat16 la = __float2bfloat16(a - __bfloat162float(ha));
    __nv_bfloat16 lb = __float2bfloat16(b - __bfloat162float(hb));
    h = pack_bf2(ha, hb);
    l = pack_bf2(la, lb);
}

// ---------------------------------------------------------------------------
// Split fp32 -> bf16 hi + lo (inputs only)
// ---------------------------------------------------------------------------
__global__ __launch_bounds__(256) void split_kernel(
    const float* __restrict__ in, __nv_bfloat16* __restrict__ hi,
    __nv_bfloat16* __restrict__ lo, int n)
{
    int i = (blockIdx.x * 256 + threadIdx.x) * 4;
    if (i >= n) return;
    float4 v = *(const float4*)(in + i);
    uint2 hv, lv;
    pack_split(v.x, v.y, hv.x, lv.x);
    pack_split(v.z, v.w, hv.y, lv.y);
    *(uint2*)(hi + i) = hv;
    *(uint2*)(lo + i) = lv;
}

// ---------------------------------------------------------------------------
// Dense GEMM via mma.sync, cp.async double-buffered.
// C[m,n] = sum_k A[m,k]*W[n,k] + bias[n]; 128x128 tile, BK=32, 8 warps.
// MODE 0: scatter bf16 hi/lo into g_Q*/g_K*/g_V* (Q scaled). MODE 1: fp32 Cout.
// ---------------------------------------------------------------------------
#define GPAD 40                   // smem row stride in bf16
#define G_ARR (128*GPAD)          // 5120 elems per matrix
#define G_STAGE (4*G_ARR)         // Ah|Al|Bh|Bl
#define GEMM_SMEM (2*G_STAGE*2)   // 81920 bytes

template<int MODE>
__global__ __launch_bounds__(256) void mma_gemm(
    const __nv_bfloat16* __restrict__ Ah, const __nv_bfloat16* __restrict__ Al,
    const __nv_bfloat16* __restrict__ Bh, const __nv_bfloat16* __restrict__ Bl,
    const float* __restrict__ bias, float* __restrict__ Cout, int N)
{
    extern __shared__ __nv_bfloat16 smp[];
    const uint32_t sm_base = smem_u32(smp);

    const int tid  = threadIdx.x;
    const int lane = tid & 31;
    const int wid  = tid >> 5;
    const int wm   = wid & 3;
    const int wn   = wid >> 2;
    const int row0 = blockIdx.y * 128;
    const int col0 = blockIdx.x * 128;
    const int grp  = lane >> 2, qp = lane & 3;

    float acc[2][8][4];
#pragma unroll
    for (int mt = 0; mt < 2; mt++)
#pragma unroll
        for (int j = 0; j < 8; j++)
#pragma unroll
            for (int c = 0; c < 4; c++) acc[mt][j][c] = 0.f;

    const int arow_off = ((lane >> 3) & 1) * 8 + (lane & 7);
    const int acol_off = (lane >> 4) * 8;
    const int brow = wn * 64 + (lane & 7);
    const int bcol_off = ((lane >> 3) & 1) * 8;

    // cp.async fill of one stage
    const int f_arr = tid >> 7;            // two arrays' worth per... (recomputed below)
    auto fill = [&](int buf, int kt) {
        const uint32_t d0 = sm_base + buf * G_STAGE * 2;
#pragma unroll
        for (int u = 0; u < 8; u++) {
            const int idx = tid + u * 256;      // 0..2047
            const int arr = idx >> 9;
            const int w   = idx & 511;
            const int r   = w >> 2;
            const int c8  = (w & 3) * 8;
            const __nv_bfloat16* src =
                (arr == 0) ? Ah + (size_t)(row0 + r) * KKC + kt + c8 :
                (arr == 1) ? Al + (size_t)(row0 + r) * KKC + kt + c8 :
                (arr == 2) ? Bh + (size_t)(col0 + r) * KKC + kt + c8 :
                             Bl + (size_t)(col0 + r) * KKC + kt + c8;
            cp16(d0 + (arr * G_ARR + r * GPAD + c8) * 2, src);
        }
        CP_COMMIT();
    };
    (void)f_arr;

    fill(0, 0);
    const int NIT = KKC / 32;     // 24
    for (int it = 0; it < NIT; it++) {
        const int buf = it & 1;
        if (it + 1 < NIT) { fill(buf ^ 1, (it + 1) * 32); CP_WAIT1(); }
        else               CP_WAIT0();
        __syncthreads();

        const uint32_t sAh = sm_base + (buf * G_STAGE) * 2;
        const uint32_t sAl = sAh + G_ARR * 2;
        const uint32_t sBh = sAh + 2 * G_ARR * 2;
        const uint32_t sBl = sAh + 3 * G_ARR * 2;

#pragma unroll
        for (int ks = 0; ks < 2; ks++) {
            uint32_t afh[2][4], afl[2][4];
#pragma unroll
            for (int mt = 0; mt < 2; mt++) {
                const int aoff = ((wm * 32 + mt * 16 + arow_off) * GPAD + ks * 16 + acol_off) * 2;
                ldsm_x4(afh[mt], sAh + aoff);
                ldsm_x4(afl[mt], sAl + aoff);
            }
#pragma unroll
            for (int j = 0; j < 8; j++) {
                uint32_t bh2[2], bl2[2];
                const int boff = ((brow + j * 8) * GPAD + ks * 16 + bcol_off) * 2;
                ldsm_x2(bh2, sBh + boff);
                ldsm_x2(bl2, sBl + boff);
#pragma unroll
                for (int mt = 0; mt < 2; mt++) {
                    mma16816(acc[mt][j], afh[mt], bh2);
                    mma16816(acc[mt][j], afh[mt], bl2);
                    mma16816(acc[mt][j], afl[mt], bh2);
                }
            }
        }
        __syncthreads();
    }

    // Epilogue
#pragma unroll
    for (int mt = 0; mt < 2; mt++) {
#pragma unroll
        for (int j = 0; j < 8; j++) {
            const int n = col0 + wn * 64 + j * 8 + qp * 2;
            const float b0 = bias[n], b1 = bias[n + 1];
#pragma unroll
            for (int rr = 0; rr < 2; rr++) {
                const int m = row0 + wm * 32 + mt * 16 + grp + rr * 8;
                float v0 = acc[mt][j][rr * 2 + 0] + b0;
                float v1 = acc[mt][j][rr * 2 + 1] + b1;
                if (MODE == 0) {
                    const int which = n / CC;
                    const int rm = n % CC;
                    const int h = rm / HS, e = rm % HS;
                    const int bb = m / TT, t = m % TT;
                    const size_t idx = ((size_t)(bb * HH + h) * TT + t) * HS + e;
                    uint32_t hw, lw;
                    if (which == 0) {
                        pack_split(v0 * SCALE_F, v1 * SCALE_F, hw, lw);
                        *(uint32_t*)&g_Qh[idx] = hw; *(uint32_t*)&g_Ql[idx] = lw;
                    } else if (which == 1) {
                        pack_split(v0, v1, hw, lw);
                        *(uint32_t*)&g_Kh[idx] = hw; *(uint32_t*)&g_Kl[idx] = lw;
                    } else {
                        pack_split(v0, v1, hw, lw);
                        *(uint32_t*)&g_Vh[idx] = hw; *(uint32_t*)&g_Vl[idx] = lw;
                    }
                } else {
                    float* p = Cout + (size_t)m * N + n;
                    *(float2*)p = make_float2(v0, v1);
                }
            }
        }
    }
}

// ---------------------------------------------------------------------------
// Flash attention via mma.sync, cp.async double-buffered bf16 K/V tiles.
// Grid (TT/128, BB*HH), 8 warps; warp owns 16 q rows; Bc=64.
// ---------------------------------------------------------------------------
#define APAD 72
#define A_ARR (64*APAD)            // 4608 elems per matrix
#define A_STAGE (4*A_ARR)          // Kh|Kl|Vh|Vl
#define ATTN_SMEM (2*A_STAGE*2)    // 73728 bytes

__global__ __launch_bounds__(256) void attn_mma()
{
    extern __shared__ __nv_bfloat16 smp[];
    const uint32_t sm_base = smem_u32(smp);

    const int tid  = threadIdx.x;
    const int lane = tid & 31;
    const int wid  = tid >> 5;
    const int qi   = blockIdx.x;
    const int bh   = blockIdx.y;
    const int q0   = qi * 128;
    const int grp  = lane >> 2, qp = lane & 3;
    const int wr0  = q0 + wid * 16;

    const size_t bh_base = (size_t)bh * TT * HS;

    // Preload Q fragments (pre-scaled, pre-split in GEMM epilogue)
    uint32_t qh[4][4], ql[4][4];
#pragma unroll
    for (int ks = 0; ks < 4; ks++) {
        const int c0 = ks * 16 + qp * 2;
        const size_t r0 = bh_base + (size_t)(wr0 + grp) * HS;
        const size_t r1 = r0 + 8 * HS;
        qh[ks][0] = *(const uint32_t*)&g_Qh[r0 + c0];
        qh[ks][1] = *(const uint32_t*)&g_Qh[r1 + c0];
        qh[ks][2] = *(const uint32_t*)&g_Qh[r0 + c0 + 8];
        qh[ks][3] = *(const uint32_t*)&g_Qh[r1 + c0 + 8];
        ql[ks][0] = *(const uint32_t*)&g_Ql[r0 + c0];
        ql[ks][1] = *(const uint32_t*)&g_Ql[r1 + c0];
        ql[ks][2] = *(const uint32_t*)&g_Ql[r0 + c0 + 8];
        ql[ks][3] = *(const uint32_t*)&g_Ql[r1 + c0 + 8];
    }

    float oacc[8][4];
    float mi[2] = {-1e30f, -1e30f}, li[2] = {0.f, 0.f};
#pragma unroll
    for (int j = 0; j < 8; j++)
#pragma unroll
        for (int c = 0; c < 4; c++) oacc[j][c] = 0.f;

    const int kb_row = (lane & 7);
    const int kb_col = ((lane >> 3) & 1) * 8;

    auto fillkv = [&](int buf, int k0) {
        const uint32_t d0 = sm_base + buf * A_STAGE * 2;
        const size_t gb = bh_base + (size_t)k0 * HS;
#pragma unroll
        for (int u = 0; u < 8; u++) {
            const int idx = tid + u * 256;      // 0..2047
            const int arr = idx >> 9;
            const int w   = idx & 511;
            const int r   = w >> 3;
            const int c8  = (w & 7) * 8;
            const __nv_bfloat16* src =
                (arr == 0) ? g_Kh + gb + (size_t)r * HS + c8 :
                (arr == 1) ? g_Kl + gb + (size_t)r * HS + c8 :
                (arr == 2) ? g_Vh + gb + (size_t)r * HS + c8 :
                             g_Vl + gb + (size_t)r * HS + c8;
            cp16(d0 + (arr * A_ARR + r * APAD + c8) * 2, src);
        }
        CP_COMMIT();
    };

    const int niters = 2 * qi + 2;
    fillkv(0, 0);
    for (int kj = 0; kj < niters; kj++) {
        const int k0 = kj * 64;
        const int buf = kj & 1;
        if (kj + 1 < niters) { fillkv(buf ^ 1, (kj + 1) * 64); CP_WAIT1(); }
        else                   CP_WAIT0();
        __syncthreads();

        if (k0 <= wr0 + 15) {
            const uint32_t sKh = sm_base + (buf * A_STAGE) * 2;
            const uint32_t sKl = sKh + A_ARR * 2;
            const uint32_t sVh = sKh + 2 * A_ARR * 2;
            const uint32_t sVl = sKh + 3 * A_ARR * 2;

            // S = Q K^T
            float sacc[8][4];
#pragma unroll
            for (int j = 0; j < 8; j++)
#pragma unroll
                for (int c = 0; c < 4; c++) sacc[j][c] = 0.f;

#pragma unroll
            for (int ks = 0; ks < 4; ks++) {
#pragma unroll
                for (int j = 0; j < 8; j++) {
                    uint32_t kbh[2], kbl[2];
                    const int off = ((j * 8 + kb_row) * APAD + ks * 16 + kb_col) * 2;
                    ldsm_x2(kbh, sKh + off);
                    ldsm_x2(kbl, sKl + off);
                    mma16816(sacc[j], qh[ks], kbh);
                    mma16816(sacc[j], qh[ks], kbl);
                    mma16816(sacc[j], ql[ks], kbh);
                }
            }

            // Causal mask for partially-masked tiles
            if (k0 + 63 > wr0) {
#pragma unroll
                for (int j = 0; j < 8; j++) {
#pragma unroll
                    for (int c = 0; c < 4; c++) {
                        const int col = k0 + j * 8 + qp * 2 + (c & 1);
                        const int row = wr0 + grp + ((c >> 1) * 8);
                        if (col > row) sacc[j][c] = -1e30f;
                    }
                }
            }

            // Online softmax
#pragma unroll
            for (int rr = 0; rr < 2; rr++) {
                float mx = -1e30f;
#pragma unroll
                for (int j = 0; j < 8; j++) {
                    mx = fmaxf(mx, sacc[j][rr * 2]);
                    mx = fmaxf(mx, sacc[j][rr * 2 + 1]);
                }
                mx = fmaxf(mx, __shfl_xor_sync(0xffffffffu, mx, 1));
                mx = fmaxf(mx, __shfl_xor_sync(0xffffffffu, mx, 2));
                const float mnew = fmaxf(mi[rr], mx);
                const float corr = __expf(mi[rr] - mnew);
                float sum = 0.f;
#pragma unroll
                for (int j = 0; j < 8; j++) {
                    float p0 = __expf(sacc[j][rr * 2]     - mnew);
                    float p1 = __expf(sacc[j][rr * 2 + 1] - mnew);
                    sacc[j][rr * 2] = p0; sacc[j][rr * 2 + 1] = p1;
                    sum += p0 + p1;
                }
                sum += __shfl_xor_sync(0xffffffffu, sum, 1);
                sum += __shfl_xor_sync(0xffffffffu, sum, 2);
                li[rr] = li[rr] * corr + sum;
                mi[rr] = mnew;
#pragma unroll
                for (int j = 0; j < 8; j++) {
                    oacc[j][rr * 2]     *= corr;
                    oacc[j][rr * 2 + 1] *= corr;
                }
            }

            // P fragments in-register
            uint32_t ph[4][4], pl[4][4];
#pragma unroll
            for (int ks = 0; ks < 4; ks++) {
                const int j0 = 2 * ks, j1 = 2 * ks + 1;
                pack_split(sacc[j0][0], sacc[j0][1], ph[ks][0], pl[ks][0]);
                pack_split(sacc[j0][2], sacc[j0][3], ph[ks][1], pl[ks][1]);
                pack_split(sacc[j1][0], sacc[j1][1], ph[ks][2], pl[ks][2]);
                pack_split(sacc[j1][2], sacc[j1][3], ph[ks][3], pl[ks][3]);
            }

            // O += P V
#pragma unroll
            for (int ks = 0; ks < 4; ks++) {
#pragma unroll
                for (int jo = 0; jo < 8; jo++) {
                    uint32_t vbh[2], vbl[2];
                    const int off = ((ks * 16 + kb_row + kb_col) * APAD + jo * 8) * 2;
                    ldsm_x2t(vbh, sVh + off);
                    ldsm_x2t(vbl, sVl + off);
                    mma16816(oacc[jo], ph[ks], vbh);
                    mma16816(oacc[jo], ph[ks], vbl);
                    mma16816(oacc[jo], pl[ks], vbh);
                }
            }
        }
        __syncthreads();
    }

    // Epilogue: write bf16 hi/lo of O/l directly (skip fp32 roundtrip)
    const int b = bh / HH, h = bh % HH;
#pragma unroll
    for (int rr = 0; rr < 2; rr++) {
        const int t = wr0 + grp + rr * 8;
        const float inv = 1.f / li[rr];
        const size_t base = (size_t)(b * TT + t) * CC + h * HS;
#pragma unroll
        for (int jo = 0; jo < 8; jo++) {
            uint32_t hw, lw;
            pack_split(oacc[jo][rr * 2] * inv, oacc[jo][rr * 2 + 1] * inv, hw, lw);
            const size_t off = base + jo * 8 + qp * 2;
            *(uint32_t*)&g_ah[off] = hw;
            *(uint32_t*)&g_al[off] = lw;
        }
    }
}

// ---------------------------------------------------------------------------
extern "C" void kernel_launch(void* const* d_in, const int* in_sizes, int n_in,
                              void* d_out, int out_size)
{
    const float* x      = (const float*)d_in[0];
    const float* w_attn = (const float*)d_in[1];
    const float* b_attn = (const float*)d_in[2];
    const float* w_proj = (const float*)d_in[3];
    const float* b_proj = (const float*)d_in[4];
    float* out = (float*)d_out;
    (void)in_sizes; (void)n_in; (void)out_size;

    __nv_bfloat16 *xh, *xl, *wah, *wal, *wph, *wpl, *ah, *al;
    cudaGetSymbolAddress((void**)&xh,  g_xh);  cudaGetSymbolAddress((void**)&xl,  g_xl);
    cudaGetSymbolAddress((void**)&wah, g_wah); cudaGetSymbolAddress((void**)&wal, g_wal);
    cudaGetSymbolAddress((void**)&wph, g_wph); cudaGetSymbolAddress((void**)&wpl, g_wpl);
    cudaGetSymbolAddress((void**)&ah,  g_ah);  cudaGetSymbolAddress((void**)&al,  g_al);

    cudaFuncSetAttribute(mma_gemm<0>, cudaFuncAttributeMaxDynamicSharedMemorySize, GEMM_SMEM);
    cudaFuncSetAttribute(mma_gemm<1>, cudaFuncAttributeMaxDynamicSharedMemorySize, GEMM_SMEM);
    cudaFuncSetAttribute(attn_mma,    cudaFuncAttributeMaxDynamicSharedMemorySize, ATTN_SMEM);

    // 0) split inputs
    split_kernel<<<(MM*CC/4 + 255)/256, 256>>>(x, xh, xl, MM*CC);
    split_kernel<<<(3*CC*CC/4 + 255)/256, 256>>>(w_attn, wah, wal, 3*CC*CC);
    split_kernel<<<(CC*CC/4 + 255)/256, 256>>>(w_proj, wph, wpl, CC*CC);

    // 1) QKV projection -> pre-split, pre-scaled Q/K/V (bf16 hi/lo)
    mma_gemm<0><<<dim3(3*CC/128, MM/128), 256, GEMM_SMEM>>>(xh, xl, wah, wal, b_attn, nullptr, 3*CC);

    // 2) Flash attention (tensor cores, bf16 pipeline) -> g_ah/g_al
    attn_mma<<<dim3(TT/128, BB*HH), 256, ATTN_SMEM>>>();

    // 3) Output projection
    mma_gemm<1><<<dim3(CC/128, MM/128), 256, GEMM_SMEM>>>(ah, al, wph, wpl, b_proj, out, CC);
}

// round 5
// speedup vs baseline: 4.3836x; 1.2956x over previous
#include <cuda_runtime.h>
#include <cuda_bf16.h>
#include <cstdint>

// Problem constants
#define BB 2
#define TT 4096
#define CC 768
#define HH 12
#define HS 64
#define MM (BB*TT)          // 8192
#define KKC 768
#define SCALE_F 0.125f      // HS^-0.5

// ---------------------------------------------------------------------------
// Scratch (allocation-free: __device__ globals) — all bf16 hi/lo pairs
// ---------------------------------------------------------------------------
__device__ __nv_bfloat16 g_Qh[BB*HH*TT*HS], g_Ql[BB*HH*TT*HS];   // scaled Q
__device__ __nv_bfloat16 g_Kh[BB*HH*TT*HS], g_Kl[BB*HH*TT*HS];
__device__ __nv_bfloat16 g_Vh[BB*HH*TT*HS], g_Vl[BB*HH*TT*HS];
__device__ __nv_bfloat16 g_xh[MM*CC],    g_xl[MM*CC];
__device__ __nv_bfloat16 g_wah[3*CC*CC], g_wal[3*CC*CC];
__device__ __nv_bfloat16 g_wph[CC*CC],   g_wpl[CC*CC];
__device__ __nv_bfloat16 g_ah[MM*CC],    g_al[MM*CC];            // attn out

// ---------------------------------------------------------------------------
// Helpers
// ---------------------------------------------------------------------------
__device__ __forceinline__ uint32_t smem_u32(const void* p) {
    uint32_t r;
    asm("{ .reg .u64 t; cvta.to.shared.u64 t, %1; cvt.u32.u64 %0, t; }" : "=r"(r) : "l"(p));
    return r;
}
__device__ __forceinline__ void mma16816(float c[4], const uint32_t a[4], const uint32_t b0, const uint32_t b1) {
    asm volatile("mma.sync.aligned.m16n8k16.row.col.f32.bf16.bf16.f32 "
                 "{%0,%1,%2,%3}, {%4,%5,%6,%7}, {%8,%9}, {%0,%1,%2,%3};"
                 : "+f"(c[0]), "+f"(c[1]), "+f"(c[2]), "+f"(c[3])
                 : "r"(a[0]), "r"(a[1]), "r"(a[2]), "r"(a[3]), "r"(b0), "r"(b1));
}
__device__ __forceinline__ void ldsm_x4(uint32_t r[4], uint32_t addr) {
    asm volatile("ldmatrix.sync.aligned.m8n8.x4.shared.b16 {%0,%1,%2,%3}, [%4];"
                 : "=r"(r[0]), "=r"(r[1]), "=r"(r[2]), "=r"(r[3]) : "r"(addr));
}
__device__ __forceinline__ void ldsm_x4t(uint32_t r[4], uint32_t addr) {
    asm volatile("ldmatrix.sync.aligned.m8n8.x4.trans.shared.b16 {%0,%1,%2,%3}, [%4];"
                 : "=r"(r[0]), "=r"(r[1]), "=r"(r[2]), "=r"(r[3]) : "r"(addr));
}
__device__ __forceinline__ void cp16(uint32_t smem, const void* g) {
    asm volatile("cp.async.cg.shared.global [%0], [%1], 16;" :: "r"(smem), "l"(g));
}
#define CP_COMMIT() asm volatile("cp.async.commit_group;" ::: "memory")
#define CP_WAIT1()  asm volatile("cp.async.wait_group 1;" ::: "memory")
#define CP_WAIT0()  asm volatile("cp.async.wait_group 0;" ::: "memory")

__device__ __forceinline__ uint32_t pack_bf2(__nv_bfloat16 lo, __nv_bfloat16 hi) {
    return ((uint32_t)__bfloat16_as_ushort(hi) << 16) | (uint32_t)__bfloat16_as_ushort(lo);
}
__device__ __forceinline__ void pack_split(float a, float b, uint32_t& h, uint32_t& l) {
    __nv_bfloat16 ha = __float2bfloat16(a), hb = __float2bfloat16(b);
    __nv_bfloat16 la = __float2bfloat16(a - __bfloat162float(ha));
    __nv_bfloat16 lb = __float2bfloat16(b - __bfloat162float(hb));
    h = pack_bf2(ha, hb);
    l = pack_bf2(la, lb);
}

// ---------------------------------------------------------------------------
// Split fp32 -> bf16 hi + lo (inputs only)
// ---------------------------------------------------------------------------
__global__ __launch_bounds__(256) void split_kernel(
    const float* __restrict__ in, __nv_bfloat16* __restrict__ hi,
    __nv_bfloat16* __restrict__ lo, int n)
{
    int i = (blockIdx.x * 256 + threadIdx.x) * 4;
    if (i >= n) return;
    float4 v = *(const float4*)(in + i);
    uint2 hv, lv;
    pack_split(v.x, v.y, hv.x, lv.x);
    pack_split(v.z, v.w, hv.y, lv.y);
    *(uint2*)(hi + i) = hv;
    *(uint2*)(lo + i) = lv;
}

// ---------------------------------------------------------------------------
// Dense GEMM via mma.sync, cp.async double-buffered. 128x128 tile, BK=32.
// ---------------------------------------------------------------------------
#define GPAD 40
#define G_ARR (128*GPAD)
#define G_STAGE (4*G_ARR)
#define GEMM_SMEM (2*G_STAGE*2)

template<int MODE>
__global__ __launch_bounds__(256) void mma_gemm(
    const __nv_bfloat16* __restrict__ Ah, const __nv_bfloat16* __restrict__ Al,
    const __nv_bfloat16* __restrict__ Bh, const __nv_bfloat16* __restrict__ Bl,
    const float* __restrict__ bias, float* __restrict__ Cout, int N)
{
    extern __shared__ __nv_bfloat16 smp[];
    const uint32_t sm_base = smem_u32(smp);

    const int tid  = threadIdx.x;
    const int lane = tid & 31;
    const int wid  = tid >> 5;
    const int wm   = wid & 3;
    const int wn   = wid >> 2;
    const int row0 = blockIdx.y * 128;
    const int col0 = blockIdx.x * 128;
    const int grp  = lane >> 2, qp = lane & 3;

    float acc[2][8][4];
#pragma unroll
    for (int mt = 0; mt < 2; mt++)
#pragma unroll
        for (int j = 0; j < 8; j++)
#pragma unroll
            for (int c = 0; c < 4; c++) acc[mt][j][c] = 0.f;

    const int arow_off = ((lane >> 3) & 1) * 8 + (lane & 7);
    const int acol_off = (lane >> 4) * 8;
    // x4 B addressing: row = base + jp*16 + ((lane>>4)&1)*8 + (lane&7); col = ks*16 + ((lane>>3)&1)*8
    const int b4row = wn * 64 + ((lane >> 4) & 1) * 8 + (lane & 7);
    const int b4col = ((lane >> 3) & 1) * 8;

    auto fill = [&](int buf, int kt) {
        const uint32_t d0 = sm_base + buf * G_STAGE * 2;
#pragma unroll
        for (int u = 0; u < 8; u++) {
            const int idx = tid + u * 256;
            const int arr = idx >> 9;
            const int w   = idx & 511;
            const int r   = w >> 2;
            const int c8  = (w & 3) * 8;
            const __nv_bfloat16* src =
                (arr == 0) ? Ah + (size_t)(row0 + r) * KKC + kt + c8 :
                (arr == 1) ? Al + (size_t)(row0 + r) * KKC + kt + c8 :
                (arr == 2) ? Bh + (size_t)(col0 + r) * KKC + kt + c8 :
                             Bl + (size_t)(col0 + r) * KKC + kt + c8;
            cp16(d0 + (arr * G_ARR + r * GPAD + c8) * 2, src);
        }
        CP_COMMIT();
    };

    fill(0, 0);
    const int NIT = KKC / 32;
    for (int it = 0; it < NIT; it++) {
        const int buf = it & 1;
        if (it + 1 < NIT) { fill(buf ^ 1, (it + 1) * 32); CP_WAIT1(); }
        else               CP_WAIT0();
        __syncthreads();

        const uint32_t sAh = sm_base + (buf * G_STAGE) * 2;
        const uint32_t sAl = sAh + G_ARR * 2;
        const uint32_t sBh = sAh + 2 * G_ARR * 2;
        const uint32_t sBl = sAh + 3 * G_ARR * 2;

#pragma unroll
        for (int ks = 0; ks < 2; ks++) {
            uint32_t afh[2][4], afl[2][4];
#pragma unroll
            for (int mt = 0; mt < 2; mt++) {
                const int aoff = ((wm * 32 + mt * 16 + arow_off) * GPAD + ks * 16 + acol_off) * 2;
                ldsm_x4(afh[mt], sAh + aoff);
                ldsm_x4(afl[mt], sAl + aoff);
            }
#pragma unroll
            for (int jp = 0; jp < 4; jp++) {
                uint32_t bh4[4], bl4[4];
                const int boff = ((b4row + jp * 16) * GPAD + ks * 16 + b4col) * 2;
                ldsm_x4(bh4, sBh + boff);
                ldsm_x4(bl4, sBl + boff);
#pragma unroll
                for (int mt = 0; mt < 2; mt++) {
                    mma16816(acc[mt][2*jp],   afh[mt], bh4[0], bh4[1]);
                    mma16816(acc[mt][2*jp],   afh[mt], bl4[0], bl4[1]);
                    mma16816(acc[mt][2*jp],   afl[mt], bh4[0], bh4[1]);
                    mma16816(acc[mt][2*jp+1], afh[mt], bh4[2], bh4[3]);
                    mma16816(acc[mt][2*jp+1], afh[mt], bl4[2], bl4[3]);
                    mma16816(acc[mt][2*jp+1], afl[mt], bh4[2], bh4[3]);
                }
            }
        }
        __syncthreads();
    }

    // Epilogue
#pragma unroll
    for (int mt = 0; mt < 2; mt++) {
#pragma unroll
        for (int j = 0; j < 8; j++) {
            const int n = col0 + wn * 64 + j * 8 + qp * 2;
            const float b0 = bias[n], b1 = bias[n + 1];
#pragma unroll
            for (int rr = 0; rr < 2; rr++) {
                const int m = row0 + wm * 32 + mt * 16 + grp + rr * 8;
                float v0 = acc[mt][j][rr * 2 + 0] + b0;
                float v1 = acc[mt][j][rr * 2 + 1] + b1;
                if (MODE == 0) {
                    const int which = n / CC;
                    const int rm = n % CC;
                    const int h = rm / HS, e = rm % HS;
                    const int bb = m / TT, t = m % TT;
                    const size_t idx = ((size_t)(bb * HH + h) * TT + t) * HS + e;
                    uint32_t hw, lw;
                    if (which == 0) {
                        pack_split(v0 * SCALE_F, v1 * SCALE_F, hw, lw);
                        *(uint32_t*)&g_Qh[idx] = hw; *(uint32_t*)&g_Ql[idx] = lw;
                    } else if (which == 1) {
                        pack_split(v0, v1, hw, lw);
                        *(uint32_t*)&g_Kh[idx] = hw; *(uint32_t*)&g_Kl[idx] = lw;
                    } else {
                        pack_split(v0, v1, hw, lw);
                        *(uint32_t*)&g_Vh[idx] = hw; *(uint32_t*)&g_Vl[idx] = lw;
                    }
                } else {
                    float* p = Cout + (size_t)m * N + n;
                    *(float2*)p = make_float2(v0, v1);
                }
            }
        }
    }
}

// ---------------------------------------------------------------------------
// Flash attention. 1-D grid (768), LPT schedule: qi = 31 - bid/24, bh = bid%24.
// 8 warps x 16 q rows; Bc=64; Q fragments in SMEM (register relief -> 2 CTA/SM).
// ---------------------------------------------------------------------------
#define APAD 72
#define A_ARR (64*APAD)                 // elems per matrix
#define A_STAGE (4*A_ARR)               // Kh|Kl|Vh|Vl
#define QFRAG_B (8*4*8*32*4)            // 32768 bytes
#define ATTN_SMEM (2*A_STAGE*2 + QFRAG_B)   // 73728 + 32768 = 106496

__global__ __launch_bounds__(256, 2) void attn_mma()
{
    extern __shared__ __nv_bfloat16 smp[];
    const uint32_t sm_base = smem_u32(smp);
    uint32_t* qsm = (uint32_t*)((char*)smp + 2 * A_STAGE * 2);

    const int tid  = threadIdx.x;
    const int lane = tid & 31;
    const int wid  = tid >> 5;
    const int qi   = (TT/128 - 1) - (blockIdx.x / (BB*HH));
    const int bh   = blockIdx.x % (BB*HH);
    const int q0   = qi * 128;
    const int grp  = lane >> 2, qp = lane & 3;
    const int wr0  = q0 + wid * 16;

    const size_t bh_base = (size_t)bh * TT * HS;

    // Build Q fragments once -> per-warp SMEM [wid][ks][reg 0-3 hi,4-7 lo][lane]
    {
#pragma unroll
        for (int ks = 0; ks < 4; ks++) {
            const int c0 = ks * 16 + qp * 2;
            const size_t r0 = bh_base + (size_t)(wr0 + grp) * HS;
            const size_t r1 = r0 + 8 * HS;
            uint32_t* q0p = &qsm[((wid * 4 + ks) * 8) * 32 + lane];
            q0p[0*32] = *(const uint32_t*)&g_Qh[r0 + c0];
            q0p[1*32] = *(const uint32_t*)&g_Qh[r1 + c0];
            q0p[2*32] = *(const uint32_t*)&g_Qh[r0 + c0 + 8];
            q0p[3*32] = *(const uint32_t*)&g_Qh[r1 + c0 + 8];
            q0p[4*32] = *(const uint32_t*)&g_Ql[r0 + c0];
            q0p[5*32] = *(const uint32_t*)&g_Ql[r1 + c0];
            q0p[6*32] = *(const uint32_t*)&g_Ql[r0 + c0 + 8];
            q0p[7*32] = *(const uint32_t*)&g_Ql[r1 + c0 + 8];
        }
    }

    float oacc[8][4];
    float mi[2] = {-1e30f, -1e30f}, li[2] = {0.f, 0.f};
#pragma unroll
    for (int j = 0; j < 8; j++)
#pragma unroll
        for (int c = 0; c < 4; c++) oacc[j][c] = 0.f;

    // x4 addressing pieces
    const int k4row = ((lane >> 4) & 1) * 8 + (lane & 7);     // within jp*16 block
    const int k4col = ((lane >> 3) & 1) * 8;
    const int v4row = ((lane >> 3) & 1) * 8 + (lane & 7);     // k-rows within ks*16
    const int v4col = ((lane >> 4) & 1) * 8;                  // jo selector within pair

    auto fillkv = [&](int buf, int k0) {
        const uint32_t d0 = sm_base + buf * A_STAGE * 2;
        const size_t gb = bh_base + (size_t)k0 * HS;
#pragma unroll
        for (int u = 0; u < 8; u++) {
            const int idx = tid + u * 256;
            const int arr = idx >> 9;
            const int w   = idx & 511;
            const int r   = w >> 3;
            const int c8  = (w & 7) * 8;
            const __nv_bfloat16* src =
                (arr == 0) ? g_Kh + gb + (size_t)r * HS + c8 :
                (arr == 1) ? g_Kl + gb + (size_t)r * HS + c8 :
                (arr == 2) ? g_Vh + gb + (size_t)r * HS + c8 :
                             g_Vl + gb + (size_t)r * HS + c8;
            cp16(d0 + (arr * A_ARR + r * APAD + c8) * 2, src);
        }
        CP_COMMIT();
    };

    const int niters = 2 * qi + 2;
    fillkv(0, 0);
    for (int kj = 0; kj < niters; kj++) {
        const int k0 = kj * 64;
        const int buf = kj & 1;
        if (kj + 1 < niters) { fillkv(buf ^ 1, (kj + 1) * 64); CP_WAIT1(); }
        else                   CP_WAIT0();
        __syncthreads();

        if (k0 <= wr0 + 15) {
            const uint32_t sKh = sm_base + (buf * A_STAGE) * 2;
            const uint32_t sKl = sKh + A_ARR * 2;
            const uint32_t sVh = sKh + 2 * A_ARR * 2;
            const uint32_t sVl = sKh + 3 * A_ARR * 2;

            // S = Q K^T
            float sacc[8][4];
#pragma unroll
            for (int j = 0; j < 8; j++)
#pragma unroll
                for (int c = 0; c < 4; c++) sacc[j][c] = 0.f;

#pragma unroll
            for (int ks = 0; ks < 4; ks++) {
                uint32_t qfh[4], qfl[4];
                const uint32_t* qp0 = &qsm[((wid * 4 + ks) * 8) * 32 + lane];
#pragma unroll
                for (int r = 0; r < 4; r++) { qfh[r] = qp0[r*32]; qfl[r] = qp0[(r+4)*32]; }
#pragma unroll
                for (int jp = 0; jp < 4; jp++) {
                    uint32_t kbh[4], kbl[4];
                    const int off = ((jp * 16 + k4row) * APAD + ks * 16 + k4col) * 2;
                    ldsm_x4(kbh, sKh + off);
                    ldsm_x4(kbl, sKl + off);
                    mma16816(sacc[2*jp],   qfh, kbh[0], kbh[1]);
                    mma16816(sacc[2*jp],   qfh, kbl[0], kbl[1]);
                    mma16816(sacc[2*jp],   qfl, kbh[0], kbh[1]);
                    mma16816(sacc[2*jp+1], qfh, kbh[2], kbh[3]);
                    mma16816(sacc[2*jp+1], qfh, kbl[2], kbl[3]);
                    mma16816(sacc[2*jp+1], qfl, kbh[2], kbh[3]);
                }
            }

            // Causal mask (partially-masked tiles only)
            if (k0 + 63 > wr0) {
#pragma unroll
                for (int j = 0; j < 8; j++) {
#pragma unroll
                    for (int c = 0; c < 4; c++) {
                        const int col = k0 + j * 8 + qp * 2 + (c & 1);
                        const int row = wr0 + grp + ((c >> 1) * 8);
                        if (col > row) sacc[j][c] = -1e30f;
                    }
                }
            }

            // Online softmax
#pragma unroll
            for (int rr = 0; rr < 2; rr++) {
                float mx = -1e30f;
#pragma unroll
                for (int j = 0; j < 8; j++) {
                    mx = fmaxf(mx, sacc[j][rr * 2]);
                    mx = fmaxf(mx, sacc[j][rr * 2 + 1]);
                }
                mx = fmaxf(mx, __shfl_xor_sync(0xffffffffu, mx, 1));
                mx = fmaxf(mx, __shfl_xor_sync(0xffffffffu, mx, 2));
                const float mnew = fmaxf(mi[rr], mx);
                const float corr = __expf(mi[rr] - mnew);
                float sum = 0.f;
#pragma unroll
                for (int j = 0; j < 8; j++) {
                    float p0 = __expf(sacc[j][rr * 2]     - mnew);
                    float p1 = __expf(sacc[j][rr * 2 + 1] - mnew);
                    sacc[j][rr * 2] = p0; sacc[j][rr * 2 + 1] = p1;
                    sum += p0 + p1;
                }
                sum += __shfl_xor_sync(0xffffffffu, sum, 1);
                sum += __shfl_xor_sync(0xffffffffu, sum, 2);
                li[rr] = li[rr] * corr + sum;
                mi[rr] = mnew;
#pragma unroll
                for (int j = 0; j < 8; j++) {
                    oacc[j][rr * 2]     *= corr;
                    oacc[j][rr * 2 + 1] *= corr;
                }
            }

            // P fragments in-register
            uint32_t ph[4][4], pl[4][4];
#pragma unroll
            for (int ks = 0; ks < 4; ks++) {
                const int j0 = 2 * ks, j1 = 2 * ks + 1;
                pack_split(sacc[j0][0], sacc[j0][1], ph[ks][0], pl[ks][0]);
                pack_split(sacc[j0][2], sacc[j0][3], ph[ks][1], pl[ks][1]);
                pack_split(sacc[j1][0], sacc[j1][1], ph[ks][2], pl[ks][2]);
                pack_split(sacc[j1][2], sacc[j1][3], ph[ks][3], pl[ks][3]);
            }

            // O += P V  (x4 trans pairs two jo blocks)
#pragma unroll
            for (int ks = 0; ks < 4; ks++) {
#pragma unroll
                for (int jop = 0; jop < 4; jop++) {
                    uint32_t vbh[4], vbl[4];
                    const int off = ((ks * 16 + v4row) * APAD + (2*jop) * 8 + v4col) * 2;
                    ldsm_x4t(vbh, sVh + off);
                    ldsm_x4t(vbl, sVl + off);
                    mma16816(oacc[2*jop],   ph[ks], vbh[0], vbh[1]);
                    mma16816(oacc[2*jop],   ph[ks], vbl[0], vbl[1]);
                    mma16816(oacc[2*jop],   pl[ks], vbh[0], vbh[1]);
                    mma16816(oacc[2*jop+1], ph[ks], vbh[2], vbh[3]);
                    mma16816(oacc[2*jop+1], ph[ks], vbl[2], vbl[3]);
                    mma16816(oacc[2*jop+1], pl[ks], vbh[2], vbh[3]);
                }
            }
        }
        __syncthreads();
    }

    // Epilogue: write bf16 hi/lo of O directly
    const int b = bh / HH, h = bh % HH;
#pragma unroll
    for (int rr = 0; rr < 2; rr++) {
        const int t = wr0 + grp + rr * 8;
        const float inv = 1.f / li[rr];
        const size_t base = (size_t)(b * TT + t) * CC + h * HS;
#pragma unroll
        for (int jo = 0; jo < 8; jo++) {
            uint32_t hw, lw;
            pack_split(oacc[jo][rr * 2] * inv, oacc[jo][rr * 2 + 1] * inv, hw, lw);
            const size_t off = base + jo * 8 + qp * 2;
            *(uint32_t*)&g_ah[off] = hw;
            *(uint32_t*)&g_al[off] = lw;
        }
    }
}

// ---------------------------------------------------------------------------
extern "C" void kernel_launch(void* const* d_in, const int* in_sizes, int n_in,
                              void* d_out, int out_size)
{
    const float* x      = (const float*)d_in[0];
    const float* w_attn = (const float*)d_in[1];
    const float* b_attn = (const float*)d_in[2];
    const float* w_proj = (const float*)d_in[3];
    const float* b_proj = (const float*)d_in[4];
    float* out = (float*)d_out;
    (void)in_sizes; (void)n_in; (void)out_size;

    __nv_bfloat16 *xh, *xl, *wah, *wal, *wph, *wpl, *ah, *al;
    cudaGetSymbolAddress((void**)&xh,  g_xh);  cudaGetSymbolAddress((void**)&xl,  g_xl);
    cudaGetSymbolAddress((void**)&wah, g_wah); cudaGetSymbolAddress((void**)&wal, g_wal);
    cudaGetSymbolAddress((void**)&wph, g_wph); cudaGetSymbolAddress((void**)&wpl, g_wpl);
    cudaGetSymbolAddress((void**)&ah,  g_ah);  cudaGetSymbolAddress((void**)&al,  g_al);

    cudaFuncSetAttribute(mma_gemm<0>, cudaFuncAttributeMaxDynamicSharedMemorySize, GEMM_SMEM);
    cudaFuncSetAttribute(mma_gemm<1>, cudaFuncAttributeMaxDynamicSharedMemorySize, GEMM_SMEM);
    cudaFuncSetAttribute(attn_mma,    cudaFuncAttributeMaxDynamicSharedMemorySize, ATTN_SMEM);

    // 0) split inputs
    split_kernel<<<(MM*CC/4 + 255)/256, 256>>>(x, xh, xl, MM*CC);
    split_kernel<<<(3*CC*CC/4 + 255)/256, 256>>>(w_attn, wah, wal, 3*CC*CC);
    split_kernel<<<(CC*CC/4 + 255)/256, 256>>>(w_proj, wph, wpl, CC*CC);

    // 1) QKV projection -> pre-split, pre-scaled Q/K/V (bf16 hi/lo)
    mma_gemm<0><<<dim3(3*CC/128, MM/128), 256, GEMM_SMEM>>>(xh, xl, wah, wal, b_attn, nullptr, 3*CC);

    // 2) Flash attention (LPT 1-D grid)
    attn_mma<<<(TT/128) * BB * HH, 256, ATTN_SMEM>>>();

    // 3) Output projection
    mma_gemm<1><<<dim3(CC/128, MM/128), 256, GEMM_SMEM>>>(ah, al, wph, wpl, b_proj, out, CC);
}